// round 11
// baseline (speedup 1.0000x reference)
#include <cuda_runtime.h>
#include <cuda_bf16.h>
#include <cstdint>

#define NN 50000
#define NE 600000
#define D  128
#define NUM_LAYER 5
#define BN_EPS 1e-5f
#define SCAN_BLOCKS 49   // ceil(50000/1024)

// ---------------- scratch (static device globals; no allocation) ----------------
__device__ float g_h  [NN * D];     // node features after input embedding
__device__ float g_h2 [NN * D];     // after Linear2 (pre-BN)
__device__ __nv_bfloat16 g_agg_hi[NN * D];
__device__ __nv_bfloat16 g_agg_lo[NN * D];
__device__ __nv_bfloat16 g_t_hi[NN * 256];
__device__ __nv_bfloat16 g_t_lo[NN * 256];
__device__ __nv_bfloat16 g_w1t_hi[NUM_LAYER * 256 * 128];  // [l][n][k]
__device__ __nv_bfloat16 g_w1t_lo[NUM_LAYER * 256 * 128];
__device__ __nv_bfloat16 g_w2t_hi[NUM_LAYER * 128 * 256];  // [l][n][k]
__device__ __nv_bfloat16 g_w2t_lo[NUM_LAYER * 128 * 256];
__device__ int   g_deg[NN];
__device__ int   g_off[NN + 1];
__device__ int   g_cur[NN];
__device__ int   g_src [NE];
__device__ int   g_code[NE];
__device__ int   g_bsum[SCAN_BLOCKS];
__device__ int   g_boff[SCAN_BLOCKS];
__device__ float g_sum1[D];
__device__ float g_sum2[D];
__device__ float g_scale[D];
__device__ float g_shift[D];

// ---------------- small helpers ----------------
__device__ __forceinline__ uint32_t smem_u32(const void* p) {
    uint32_t a;
    asm("{ .reg .u64 t; cvta.to.shared.u64 t, %1; cvt.u32.u64 %0, t; }" : "=r"(a) : "l"(p));
    return a;
}
__device__ __forceinline__ void split2(float a, float b, uint32_t& h, uint32_t& l) {
    __nv_bfloat16 ah = __float2bfloat16(a), bh = __float2bfloat16(b);
    __nv_bfloat16 al = __float2bfloat16(a - __bfloat162float(ah));
    __nv_bfloat16 bl = __float2bfloat16(b - __bfloat162float(bh));
    __nv_bfloat162 hh; hh.x = ah; hh.y = bh;
    __nv_bfloat162 ll; ll.x = al; ll.y = bl;
    h = *(uint32_t*)&hh;
    l = *(uint32_t*)&ll;
}
__device__ __forceinline__ void ldm4(uint32_t& r0, uint32_t& r1, uint32_t& r2, uint32_t& r3,
                                     uint32_t addr) {
    asm volatile("ldmatrix.sync.aligned.m8n8.x4.shared.b16 {%0,%1,%2,%3}, [%4];"
                 : "=r"(r0), "=r"(r1), "=r"(r2), "=r"(r3) : "r"(addr));
}
__device__ __forceinline__ void mma_bf16(float* c, const uint32_t* a, const uint32_t* b) {
    asm volatile(
        "mma.sync.aligned.m16n8k16.row.col.f32.bf16.bf16.f32 "
        "{%0,%1,%2,%3},{%4,%5,%6,%7},{%8,%9},{%0,%1,%2,%3};"
        : "+f"(c[0]), "+f"(c[1]), "+f"(c[2]), "+f"(c[3])
        : "r"(a[0]), "r"(a[1]), "r"(a[2]), "r"(a[3]), "r"(b[0]), "r"(b[1]));
}

// ---------------- preamble kernels ----------------

__global__ void k_embed(const int* __restrict__ x,
                        const float* __restrict__ ae,
                        const float* __restrict__ ce,
                        const float* __restrict__ he) {
    int idx = blockIdx.x * blockDim.x + threadIdx.x;       // over NN*32
    if (idx >= NN * 32) return;
    int n  = idx >> 5;
    int c4 = (idx & 31) * 4;
    int x0 = x[n * 3 + 0], x1 = x[n * 3 + 1], x2 = x[n * 3 + 2];
    float4 a = *(const float4*)&ae[x0 * D + c4];
    float4 b = *(const float4*)&ce[x1 * D + c4];
    float4 c = *(const float4*)&he[x2 * D + c4];
    float4 o;
    o.x = a.x + b.x + c.x; o.y = a.y + b.y + c.y;
    o.z = a.z + b.z + c.z; o.w = a.w + b.w + c.w;
    *(float4*)&g_h[n * D + c4] = o;
}

__global__ void k_prepw(const float* __restrict__ W1, const float* __restrict__ W2) {
    int i = blockIdx.x * blockDim.x + threadIdx.x;
    if (i >= NUM_LAYER * 256 * 128) return;
    {
        int l = i / (256 * 128), rem = i % (256 * 128);
        int n = rem >> 7, k = rem & 127;
        float v = W1[(l * 128 + k) * 256 + n];
        __nv_bfloat16 h = __float2bfloat16(v);
        g_w1t_hi[i] = h;
        g_w1t_lo[i] = __float2bfloat16(v - __bfloat162float(h));
    }
    {
        int l = i / (128 * 256), rem = i % (128 * 256);
        int n = rem >> 8, k = rem & 255;
        float v = W2[(l * 256 + k) * 128 + n];
        __nv_bfloat16 h = __float2bfloat16(v);
        g_w2t_hi[i] = h;
        g_w2t_lo[i] = __float2bfloat16(v - __bfloat162float(h));
    }
}

__global__ void k_zero_deg() {
    int i = blockIdx.x * blockDim.x + threadIdx.x;
    if (i < NN) g_deg[i] = 0;
}

__global__ void k_count(const int* __restrict__ ei) {
    int e = blockIdx.x * blockDim.x + threadIdx.x;
    if (e < NE) atomicAdd(&g_deg[ei[NE + e]], 1);
}

__global__ void k_scan1() {
    __shared__ int swarp[32];
    int tid = threadIdx.x;
    int i = blockIdx.x * 1024 + tid;
    int v = (i < NN) ? g_deg[i] : 0;
    int x = v;
#pragma unroll
    for (int o = 1; o < 32; o <<= 1) {
        int t = __shfl_up_sync(0xffffffffu, x, o);
        if ((tid & 31) >= o) x += t;
    }
    if ((tid & 31) == 31) swarp[tid >> 5] = x;
    __syncthreads();
    if (tid < 32) {
        int y = swarp[tid];
#pragma unroll
        for (int o = 1; o < 32; o <<= 1) {
            int t = __shfl_up_sync(0xffffffffu, y, o);
            if (tid >= o) y += t;
        }
        swarp[tid] = y;
    }
    __syncthreads();
    int off = (tid >= 32) ? swarp[(tid >> 5) - 1] : 0;
    int incl = x + off;
    if (i < NN) g_off[i] = incl - v;
    if (tid == 1023) g_bsum[blockIdx.x] = incl;
}

__global__ void k_scan2() {
    int acc = 0;
#pragma unroll
    for (int b = 0; b < SCAN_BLOCKS; b++) {
        int t = g_bsum[b];
        g_boff[b] = acc;
        acc += t;
    }
    g_off[NN] = acc;
}

__global__ void k_scan3() {
    int i = blockIdx.x * 1024 + threadIdx.x;
    if (i < NN) {
        int o = g_off[i] + g_boff[i >> 10];
        g_off[i] = o;
        g_cur[i] = o;
    }
}

__global__ void k_fill(const int* __restrict__ ei, const int* __restrict__ ea) {
    int e = blockIdx.x * blockDim.x + threadIdx.x;
    if (e >= NE) return;
    int d = ei[NE + e];
    int p = atomicAdd(&g_cur[d], 1);
    g_src[p]  = ei[e];
    g_code[p] = ea[2 * e] * 4 + ea[2 * e + 1];
}

// warp-per-node aggregation (R8-proven shape: 8 nodes/block, max warp parallelism).
// fuse=1 applies previous layer's BN+ReLU to gathered rows.
// Block 0 zeroes the BN-stat accumulators for this layer's GEMM2.
__global__ void k_agg(const float* __restrict__ e1l, const float* __restrict__ e2l,
                      const float* __restrict__ hin, int fuse) {
    __shared__ __align__(16) float see[24 * D];
    for (int i = threadIdx.x; i < 24 * D; i += 256) {
        int c = i >> 7, k = i & 127;
        see[i] = e1l[(c >> 2) * D + k] + e2l[(c & 3) * D + k];
    }
    if (blockIdx.x == 0) {
        int t = threadIdx.x;
        if (t < 128) g_sum1[t] = 0.f;
        else if (t < 256) g_sum2[t - 128] = 0.f;
    }
    __syncthreads();
    int warp = threadIdx.x >> 5;
    int lane = threadIdx.x & 31;
    int n = blockIdx.x * 8 + warp;
    if (n >= NN) return;
    int c4 = lane * 4;
    float4 sc = make_float4(1.f, 1.f, 1.f, 1.f);
    float4 sh = make_float4(0.f, 0.f, 0.f, 0.f);
    if (fuse) {
        sc = *(const float4*)&g_scale[c4];
        sh = *(const float4*)&g_shift[c4];
    }
    float4 acc = make_float4(0.f, 0.f, 0.f, 0.f);
    int b = g_off[n], e = g_off[n + 1];
    for (int j = b; j < e; j++) {
        int s0 = g_src[j], c0 = g_code[j];
        float4 h0 = *(const float4*)&hin[s0 * D + c4];
        float4 e0 = *(const float4*)&see[c0 * D + c4];
        if (fuse) {
            h0.x = fmaxf(fmaf(sc.x, h0.x, sh.x), 0.f);
            h0.y = fmaxf(fmaf(sc.y, h0.y, sh.y), 0.f);
            h0.z = fmaxf(fmaf(sc.z, h0.z, sh.z), 0.f);
            h0.w = fmaxf(fmaf(sc.w, h0.w, sh.w), 0.f);
        }
        acc.x += h0.x + e0.x;
        acc.y += h0.y + e0.y;
        acc.z += h0.z + e0.z;
        acc.w += h0.w + e0.w;
    }
    uint32_t h01, l01, h23, l23;
    split2(acc.x, acc.y, h01, l01);
    split2(acc.z, acc.w, h23, l23);
    uint2 uh; uh.x = h01; uh.y = h23;
    uint2 ul; ul.x = l01; ul.y = l23;
    *(uint2*)&g_agg_hi[n * D + c4] = uh;
    *(uint2*)&g_agg_lo[n * D + c4] = ul;
}

// ---------------- mma.sync bf16-split GEMM (R8-proven structure) ----------------
// C[M,NC] = A[M,K]·Bt[NC,K]^T, A=Ahi+Alo, B=Bhi+Blo (bf16 split):
// C ≈ Ahi·Bhi + Ahi·Blo + Alo·Bhi  (fp32 accumulate)
// BM=128, BN=64, BK=64. 256 thr = 8 warps (4x2), warp tile 32x32.
// relu_mode=1: bias+relu, split to bf16 hi/lo outputs.
// relu_mode=0: bias, fp32 output + fused BN column stats (atomicAdd to g_sum).
#define SA_HI 0
#define SA_LO 16384
#define SB_HI 32768
#define SB_LO 40960
#define SM_TOTAL 49152

__device__ __forceinline__ void ldTileA(char* sm, int soff,
                                        const __nv_bfloat16* __restrict__ src,
                                        int row0, int stride, int k0, int mval) {
#pragma unroll
    for (int i = 0; i < 4; i++) {
        int t = threadIdx.x + i * 256;
        int r = t >> 3, c8 = t & 7;
        uint4 v = make_uint4(0u, 0u, 0u, 0u);
        if (r < mval) v = *(const uint4*)&src[(long)(row0 + r) * stride + k0 + c8 * 8];
        *(uint4*)(sm + soff + r * 128 + ((c8 ^ (r & 7)) << 4)) = v;
    }
}
__device__ __forceinline__ void ldTileB(char* sm, int soff,
                                        const __nv_bfloat16* __restrict__ src,
                                        int row0, int stride, int k0) {
#pragma unroll
    for (int i = 0; i < 2; i++) {
        int t = threadIdx.x + i * 256;
        int r = t >> 3, c8 = t & 7;
        uint4 v = *(const uint4*)&src[(long)(row0 + r) * stride + k0 + c8 * 8];
        *(uint4*)(sm + soff + r * 128 + ((c8 ^ (r & 7)) << 4)) = v;
    }
}

__global__ void __launch_bounds__(256)
k_gemm_mma(const __nv_bfloat16* __restrict__ Ahi, const __nv_bfloat16* __restrict__ Alo,
           const __nv_bfloat16* __restrict__ Bhi, const __nv_bfloat16* __restrict__ Blo,
           const float* __restrict__ bias,
           float* __restrict__ outF,
           __nv_bfloat16* __restrict__ outHi, __nv_bfloat16* __restrict__ outLo,
           int M, int Kin, int NC, int relu_mode) {
    extern __shared__ char sm[];
    uint32_t sb = smem_u32(sm);
    int tid = threadIdx.x, wid = tid >> 5, lane = tid & 31;
    int wm = wid >> 1, wn = wid & 1;
    int m0 = blockIdx.x * 128;
    int n0 = blockIdx.y * 64;
    int mvalid = M - m0; if (mvalid > 128) mvalid = 128;

    float acc[2][4][4];
#pragma unroll
    for (int mt = 0; mt < 2; mt++)
#pragma unroll
        for (int nt = 0; nt < 4; nt++)
#pragma unroll
            for (int q = 0; q < 4; q++) acc[mt][nt][q] = 0.f;

    int chunks = Kin >> 6;
    for (int ch = 0; ch < chunks; ch++) {
        int k0 = ch << 6;
        ldTileA(sm, SA_HI, Ahi, m0, Kin, k0, mvalid);
        ldTileA(sm, SA_LO, Alo, m0, Kin, k0, mvalid);
        ldTileB(sm, SB_HI, Bhi, n0, Kin, k0);
        ldTileB(sm, SB_LO, Blo, n0, Kin, k0);
        __syncthreads();

#pragma unroll
        for (int ks = 0; ks < 4; ks++) {
            uint32_t ah[2][4], al[2][4], bh[4][2], bl[4][2];
            int arow_l = lane & 15;
            int ac8 = ks * 2 + (lane >> 4);
#pragma unroll
            for (int mt = 0; mt < 2; mt++) {
                int r = wm * 32 + mt * 16 + arow_l;
                uint32_t ad = sb + r * 128 + ((ac8 ^ (r & 7)) << 4);
                ldm4(ah[mt][0], ah[mt][1], ah[mt][2], ah[mt][3], ad + SA_HI);
                ldm4(al[mt][0], al[mt][1], al[mt][2], al[mt][3], ad + SA_LO);
            }
            int nrow_l = (lane & 7) + ((lane >> 4) << 3);
            int bc8 = ks * 2 + ((lane >> 3) & 1);
#pragma unroll
            for (int p = 0; p < 2; p++) {
                int r = wn * 32 + p * 16 + nrow_l;
                uint32_t bd = sb + r * 128 + ((bc8 ^ (r & 7)) << 4);
                ldm4(bh[2 * p][0], bh[2 * p][1], bh[2 * p + 1][0], bh[2 * p + 1][1], bd + SB_HI);
                ldm4(bl[2 * p][0], bl[2 * p][1], bl[2 * p + 1][0], bl[2 * p + 1][1], bd + SB_LO);
            }
#pragma unroll
            for (int mt = 0; mt < 2; mt++)
#pragma unroll
                for (int nt = 0; nt < 4; nt++) {
                    mma_bf16(acc[mt][nt], ah[mt], bh[nt]);
                    mma_bf16(acc[mt][nt], ah[mt], bl[nt]);
                    mma_bf16(acc[mt][nt], al[mt], bh[nt]);
                }
        }
        __syncthreads();
    }

    // epilogue
    if (relu_mode) {
#pragma unroll
        for (int mt = 0; mt < 2; mt++) {
            int r0 = m0 + wm * 32 + mt * 16 + (lane >> 2);
#pragma unroll
            for (int nt = 0; nt < 4; nt++) {
                int cb = n0 + wn * 32 + nt * 8 + (lane & 3) * 2;
                float b0 = bias[cb], b1 = bias[cb + 1];
                float v0 = fmaxf(acc[mt][nt][0] + b0, 0.f);
                float v1 = fmaxf(acc[mt][nt][1] + b1, 0.f);
                float v2 = fmaxf(acc[mt][nt][2] + b0, 0.f);
                float v3 = fmaxf(acc[mt][nt][3] + b1, 0.f);
                uint32_t h01, l01, h23, l23;
                split2(v0, v1, h01, l01);
                split2(v2, v3, h23, l23);
                if (r0 < M) {
                    *(uint32_t*)&outHi[(long)r0 * NC + cb] = h01;
                    *(uint32_t*)&outLo[(long)r0 * NC + cb] = l01;
                }
                if (r0 + 8 < M) {
                    *(uint32_t*)&outHi[(long)(r0 + 8) * NC + cb] = h23;
                    *(uint32_t*)&outLo[(long)(r0 + 8) * NC + cb] = l23;
                }
            }
        }
    } else {
        // fp32 store + fused BN column stats
        float st_s0[4], st_s1[4], st_q0[4], st_q1[4];
#pragma unroll
        for (int nt = 0; nt < 4; nt++) { st_s0[nt] = 0.f; st_s1[nt] = 0.f; st_q0[nt] = 0.f; st_q1[nt] = 0.f; }
#pragma unroll
        for (int mt = 0; mt < 2; mt++) {
            int r0 = m0 + wm * 32 + mt * 16 + (lane >> 2);
            int r1 = r0 + 8;
#pragma unroll
            for (int nt = 0; nt < 4; nt++) {
                int cb = n0 + wn * 32 + nt * 8 + (lane & 3) * 2;
                float b0 = bias[cb], b1 = bias[cb + 1];
                float v0 = acc[mt][nt][0] + b0;
                float v1 = acc[mt][nt][1] + b1;
                float v2 = acc[mt][nt][2] + b0;
                float v3 = acc[mt][nt][3] + b1;
                if (r0 < M) {
                    float2 p; p.x = v0; p.y = v1;
                    *(float2*)&outF[(long)r0 * NC + cb] = p;
                    st_s0[nt] += v0; st_s1[nt] += v1;
                    st_q0[nt] += v0 * v0; st_q1[nt] += v1 * v1;
                }
                if (r1 < M) {
                    float2 p; p.x = v2; p.y = v3;
                    *(float2*)&outF[(long)r1 * NC + cb] = p;
                    st_s0[nt] += v2; st_s1[nt] += v3;
                    st_q0[nt] += v2 * v2; st_q1[nt] += v3 * v3;
                }
            }
        }
#pragma unroll
        for (int nt = 0; nt < 4; nt++) {
#pragma unroll
            for (int o = 4; o < 32; o <<= 1) {
                st_s0[nt] += __shfl_xor_sync(0xffffffffu, st_s0[nt], o);
                st_s1[nt] += __shfl_xor_sync(0xffffffffu, st_s1[nt], o);
                st_q0[nt] += __shfl_xor_sync(0xffffffffu, st_q0[nt], o);
                st_q1[nt] += __shfl_xor_sync(0xffffffffu, st_q1[nt], o);
            }
            if ((lane >> 2) == 0) {
                int cb = n0 + wn * 32 + nt * 8 + (lane & 3) * 2;
                atomicAdd(&g_sum1[cb],     st_s0[nt]);
                atomicAdd(&g_sum1[cb + 1], st_s1[nt]);
                atomicAdd(&g_sum2[cb],     st_q0[nt]);
                atomicAdd(&g_sum2[cb + 1], st_q1[nt]);
            }
        }
    }
}

// ---------------- BN final / final norm ----------------
__global__ void k_bnfinal(const float* __restrict__ gamma,
                          const float* __restrict__ beta) {
    int c = threadIdx.x;
    float mu  = g_sum1[c] / (float)NN;
    float var = g_sum2[c] / (float)NN - mu * mu;
    float sc  = gamma[c] * rsqrtf(var + BN_EPS);
    g_scale[c] = sc;
    g_shift[c] = beta[c] - mu * sc;
}

__global__ void k_norm(float* __restrict__ dst) {
    int idx = blockIdx.x * blockDim.x + threadIdx.x;
    if (idx >= NN * 32) return;
    int c4 = (idx & 31) * 4;
    float4 v  = *(const float4*)&g_h2[idx * 4];
    float4 sc = *(const float4*)&g_scale[c4];
    float4 sh = *(const float4*)&g_shift[c4];
    float4 o;
    o.x = fmaf(sc.x, v.x, sh.x); o.y = fmaf(sc.y, v.y, sh.y);
    o.z = fmaf(sc.z, v.z, sh.z); o.w = fmaf(sc.w, v.w, sh.w);
    *(float4*)&dst[idx * 4] = o;
}

// ---------------- host ----------------
extern "C" void kernel_launch(void* const* d_in, const int* in_sizes, int n_in,
                              void* d_out, int out_size) {
    const int*   x     = (const int*)d_in[0];
    const int*   ei    = (const int*)d_in[1];
    const int*   ea    = (const int*)d_in[2];
    const float* ae    = (const float*)d_in[3];
    const float* ce    = (const float*)d_in[4];
    const float* he    = (const float*)d_in[5];
    const float* e1    = (const float*)d_in[6];
    const float* e2    = (const float*)d_in[7];
    const float* W1    = (const float*)d_in[8];
    const float* b1    = (const float*)d_in[9];
    const float* W2    = (const float*)d_in[10];
    const float* b2    = (const float*)d_in[11];
    const float* gamma = (const float*)d_in[12];
    const float* beta  = (const float*)d_in[13];
    float* out = (float*)d_out;

    void *p_h, *p_h2, *p_agh, *p_agl, *p_th, *p_tl, *p_w1h, *p_w1l, *p_w2h, *p_w2l;
    cudaGetSymbolAddress(&p_h,   g_h);
    cudaGetSymbolAddress(&p_h2,  g_h2);
    cudaGetSymbolAddress(&p_agh, g_agg_hi);
    cudaGetSymbolAddress(&p_agl, g_agg_lo);
    cudaGetSymbolAddress(&p_th,  g_t_hi);
    cudaGetSymbolAddress(&p_tl,  g_t_lo);
    cudaGetSymbolAddress(&p_w1h, g_w1t_hi);
    cudaGetSymbolAddress(&p_w1l, g_w1t_lo);
    cudaGetSymbolAddress(&p_w2h, g_w2t_hi);
    cudaGetSymbolAddress(&p_w2l, g_w2t_lo);
    float* hv  = (float*)p_h;
    float* h2v = (float*)p_h2;
    __nv_bfloat16* agh = (__nv_bfloat16*)p_agh;
    __nv_bfloat16* agl = (__nv_bfloat16*)p_agl;
    __nv_bfloat16* th  = (__nv_bfloat16*)p_th;
    __nv_bfloat16* tl  = (__nv_bfloat16*)p_tl;
    __nv_bfloat16* w1h = (__nv_bfloat16*)p_w1h;
    __nv_bfloat16* w1l = (__nv_bfloat16*)p_w1l;
    __nv_bfloat16* w2h = (__nv_bfloat16*)p_w2h;
    __nv_bfloat16* w2l = (__nv_bfloat16*)p_w2l;

    cudaFuncSetAttribute(k_gemm_mma, cudaFuncAttributeMaxDynamicSharedMemorySize, SM_TOTAL);

    const int vecBlocks  = (NN * 32 + 255) / 256;
    const int nodeBlocks = (NN + 255) / 256;
    const int edgeBlocks = (NE + 255) / 256;
    const int aggBlocks  = (NN + 7) / 8;         // 6250 (R8-proven)
    const int mTiles     = (NN + 127) / 128;     // 391
    const int prepBlocks = (NUM_LAYER * 256 * 128 + 255) / 256;

    k_embed<<<vecBlocks, 256>>>(x, ae, ce, he);
    k_prepw<<<prepBlocks, 256>>>(W1, W2);
    k_zero_deg<<<nodeBlocks, 256>>>();
    k_count<<<edgeBlocks, 256>>>(ei);
    k_scan1<<<SCAN_BLOCKS, 1024>>>();
    k_scan2<<<1, 1>>>();
    k_scan3<<<SCAN_BLOCKS, 1024>>>();
    k_fill<<<edgeBlocks, 256>>>(ei, ea);

    for (int l = 0; l < NUM_LAYER; l++) {
        k_agg<<<aggBlocks, 256>>>(e1 + (long)l * 6 * D, e2 + (long)l * 4 * D,
                                  (l == 0) ? hv : h2v, (l == 0) ? 0 : 1);
        // GEMM1: [NN,128] x W1t[256,128]^T -> t (bf16 hi/lo, relu)
        k_gemm_mma<<<dim3(mTiles, 4), 256, SM_TOTAL>>>(
            agh, agl,
            w1h + (long)l * 256 * 128, w1l + (long)l * 256 * 128,
            b1 + (long)l * 256,
            nullptr, th, tl,
            NN, 128, 256, 1);
        // GEMM2: [NN,256] x W2t[128,256]^T -> g_h2 (fp32) + fused BN stats
        k_gemm_mma<<<dim3(mTiles, 2), 256, SM_TOTAL>>>(
            th, tl,
            w2h + (long)l * 128 * 256, w2l + (long)l * 128 * 256,
            b2 + (long)l * D,
            h2v, nullptr, nullptr,
            NN, 256, 128, 0);
        k_bnfinal<<<1, 128>>>(gamma + (long)l * D, beta + (long)l * D);
    }
    k_norm<<<vecBlocks, 256>>>(out);
}

// round 12
// speedup vs baseline: 1.5529x; 1.5529x over previous
#include <cuda_runtime.h>
#include <cuda_bf16.h>
#include <cstdint>

#define NN 50000
#define NE 600000
#define D  128
#define NUM_LAYER 5
#define BN_EPS 1e-5f
#define STATS_BLOCKS 512
#define SCAN_BLOCKS 49   // ceil(50000/1024)

// ---------------- scratch (static device globals; no allocation) ----------------
__device__ float g_h  [NN * D];     // node features after input embedding
__device__ float g_h2 [NN * D];     // after Linear2 (pre-BN)
__device__ __nv_bfloat16 g_agg_hi[NN * D];
__device__ __nv_bfloat16 g_agg_lo[NN * D];
__device__ __nv_bfloat16 g_t_hi[NN * 256];
__device__ __nv_bfloat16 g_t_lo[NN * 256];
__device__ __nv_bfloat16 g_w1t_hi[NUM_LAYER * 256 * 128];  // [l][n][k]
__device__ __nv_bfloat16 g_w1t_lo[NUM_LAYER * 256 * 128];
__device__ __nv_bfloat16 g_w2t_hi[NUM_LAYER * 128 * 256];  // [l][n][k]
__device__ __nv_bfloat16 g_w2t_lo[NUM_LAYER * 128 * 256];
__device__ int   g_deg[NN];
__device__ int   g_off[NN + 1];
__device__ int   g_cur[NN];
__device__ int   g_src [NE];
__device__ int   g_code[NE];
__device__ int   g_bsum[SCAN_BLOCKS];
__device__ int   g_boff[SCAN_BLOCKS];
__device__ float g_p1[STATS_BLOCKS * D];
__device__ float g_p2[STATS_BLOCKS * D];
__device__ float g_scale[D];
__device__ float g_shift[D];

// ---------------- small helpers ----------------
__device__ __forceinline__ uint32_t smem_u32(const void* p) {
    uint32_t a;
    asm("{ .reg .u64 t; cvta.to.shared.u64 t, %1; cvt.u32.u64 %0, t; }" : "=r"(a) : "l"(p));
    return a;
}
__device__ __forceinline__ void split2(float a, float b, uint32_t& h, uint32_t& l) {
    __nv_bfloat16 ah = __float2bfloat16(a), bh = __float2bfloat16(b);
    __nv_bfloat16 al = __float2bfloat16(a - __bfloat162float(ah));
    __nv_bfloat16 bl = __float2bfloat16(b - __bfloat162float(bh));
    __nv_bfloat162 hh; hh.x = ah; hh.y = bh;
    __nv_bfloat162 ll; ll.x = al; ll.y = bl;
    h = *(uint32_t*)&hh;
    l = *(uint32_t*)&ll;
}
__device__ __forceinline__ void ldm4(uint32_t& r0, uint32_t& r1, uint32_t& r2, uint32_t& r3,
                                     uint32_t addr) {
    asm volatile("ldmatrix.sync.aligned.m8n8.x4.shared.b16 {%0,%1,%2,%3}, [%4];"
                 : "=r"(r0), "=r"(r1), "=r"(r2), "=r"(r3) : "r"(addr));
}
__device__ __forceinline__ void mma_bf16(float* c, const uint32_t* a, const uint32_t* b) {
    asm volatile(
        "mma.sync.aligned.m16n8k16.row.col.f32.bf16.bf16.f32 "
        "{%0,%1,%2,%3},{%4,%5,%6,%7},{%8,%9},{%0,%1,%2,%3};"
        : "+f"(c[0]), "+f"(c[1]), "+f"(c[2]), "+f"(c[3])
        : "r"(a[0]), "r"(a[1]), "r"(a[2]), "r"(a[3]), "r"(b[0]), "r"(b[1]));
}

// ---------------- preamble kernels ----------------

__global__ void k_embed(const int* __restrict__ x,
                        const float* __restrict__ ae,
                        const float* __restrict__ ce,
                        const float* __restrict__ he) {
    int idx = blockIdx.x * blockDim.x + threadIdx.x;       // over NN*32
    if (idx >= NN * 32) return;
    int n  = idx >> 5;
    int c4 = (idx & 31) * 4;
    int x0 = x[n * 3 + 0], x1 = x[n * 3 + 1], x2 = x[n * 3 + 2];
    float4 a = *(const float4*)&ae[x0 * D + c4];
    float4 b = *(const float4*)&ce[x1 * D + c4];
    float4 c = *(const float4*)&he[x2 * D + c4];
    float4 o;
    o.x = a.x + b.x + c.x; o.y = a.y + b.y + c.y;
    o.z = a.z + b.z + c.z; o.w = a.w + b.w + c.w;
    *(float4*)&g_h[n * D + c4] = o;
}

__global__ void k_prepw(const float* __restrict__ W1, const float* __restrict__ W2) {
    int i = blockIdx.x * blockDim.x + threadIdx.x;
    if (i >= NUM_LAYER * 256 * 128) return;
    {
        int l = i / (256 * 128), rem = i % (256 * 128);
        int n = rem >> 7, k = rem & 127;
        float v = W1[(l * 128 + k) * 256 + n];
        __nv_bfloat16 h = __float2bfloat16(v);
        g_w1t_hi[i] = h;
        g_w1t_lo[i] = __float2bfloat16(v - __bfloat162float(h));
    }
    {
        int l = i / (128 * 256), rem = i % (128 * 256);
        int n = rem >> 8, k = rem & 255;
        float v = W2[(l * 256 + k) * 128 + n];
        __nv_bfloat16 h = __float2bfloat16(v);
        g_w2t_hi[i] = h;
        g_w2t_lo[i] = __float2bfloat16(v - __bfloat162float(h));
    }
}

__global__ void k_zero_deg() {
    int i = blockIdx.x * blockDim.x + threadIdx.x;
    if (i < NN) g_deg[i] = 0;
}

__global__ void k_count(const int* __restrict__ ei) {
    int e = blockIdx.x * blockDim.x + threadIdx.x;
    if (e < NE) atomicAdd(&g_deg[ei[NE + e]], 1);
}

__global__ void k_scan1() {
    __shared__ int swarp[32];
    int tid = threadIdx.x;
    int i = blockIdx.x * 1024 + tid;
    int v = (i < NN) ? g_deg[i] : 0;
    int x = v;
#pragma unroll
    for (int o = 1; o < 32; o <<= 1) {
        int t = __shfl_up_sync(0xffffffffu, x, o);
        if ((tid & 31) >= o) x += t;
    }
    if ((tid & 31) == 31) swarp[tid >> 5] = x;
    __syncthreads();
    if (tid < 32) {
        int y = swarp[tid];
#pragma unroll
        for (int o = 1; o < 32; o <<= 1) {
            int t = __shfl_up_sync(0xffffffffu, y, o);
            if (tid >= o) y += t;
        }
        swarp[tid] = y;
    }
    __syncthreads();
    int off = (tid >= 32) ? swarp[(tid >> 5) - 1] : 0;
    int incl = x + off;
    if (i < NN) g_off[i] = incl - v;
    if (tid == 1023) g_bsum[blockIdx.x] = incl;
}

__global__ void k_scan2() {
    int acc = 0;
#pragma unroll
    for (int b = 0; b < SCAN_BLOCKS; b++) {
        int t = g_bsum[b];
        g_boff[b] = acc;
        acc += t;
    }
    g_off[NN] = acc;
}

__global__ void k_scan3() {
    int i = blockIdx.x * 1024 + threadIdx.x;
    if (i < NN) {
        int o = g_off[i] + g_boff[i >> 10];
        g_off[i] = o;
        g_cur[i] = o;
    }
}

__global__ void k_fill(const int* __restrict__ ei, const int* __restrict__ ea) {
    int e = blockIdx.x * blockDim.x + threadIdx.x;
    if (e >= NE) return;
    int d = ei[NE + e];
    int p = atomicAdd(&g_cur[d], 1);
    g_src[p]  = ei[e];
    g_code[p] = ea[2 * e] * 4 + ea[2 * e + 1];
}

// 4 nodes per warp (R10/R11-measured fast shape: 4 independent edge chains per
// warp quadruple memory-level parallelism). fuse=1 applies previous layer's
// BN+ReLU to gathered rows. Writes bf16 hi/lo split directly (GEMM1 input).
__global__ void k_agg(const float* __restrict__ e1l, const float* __restrict__ e2l,
                      const float* __restrict__ hin, int fuse) {
    __shared__ __align__(16) float see[24 * D];
    for (int i = threadIdx.x; i < 24 * D; i += 256) {
        int c = i >> 7, k = i & 127;
        see[i] = e1l[(c >> 2) * D + k] + e2l[(c & 3) * D + k];
    }
    __syncthreads();
    int warp = threadIdx.x >> 5;
    int lane = threadIdx.x & 31;
    int c4 = lane * 4;
    float4 sc = make_float4(1.f, 1.f, 1.f, 1.f);
    float4 sh = make_float4(0.f, 0.f, 0.f, 0.f);
    if (fuse) {
        sc = *(const float4*)&g_scale[c4];
        sh = *(const float4*)&g_shift[c4];
    }
#pragma unroll
    for (int i = 0; i < 4; i++) {
        int n = blockIdx.x * 32 + warp * 4 + i;
        if (n >= NN) continue;
        float4 acc = make_float4(0.f, 0.f, 0.f, 0.f);
        int b = g_off[n], e = g_off[n + 1];
        for (int j = b; j < e; j++) {
            int s0 = g_src[j], c0 = g_code[j];
            float4 h0 = *(const float4*)&hin[s0 * D + c4];
            float4 e0 = *(const float4*)&see[c0 * D + c4];
            if (fuse) {
                h0.x = fmaxf(fmaf(sc.x, h0.x, sh.x), 0.f);
                h0.y = fmaxf(fmaf(sc.y, h0.y, sh.y), 0.f);
                h0.z = fmaxf(fmaf(sc.z, h0.z, sh.z), 0.f);
                h0.w = fmaxf(fmaf(sc.w, h0.w, sh.w), 0.f);
            }
            acc.x += h0.x + e0.x;
            acc.y += h0.y + e0.y;
            acc.z += h0.z + e0.z;
            acc.w += h0.w + e0.w;
        }
        uint32_t h01, l01, h23, l23;
        split2(acc.x, acc.y, h01, l01);
        split2(acc.z, acc.w, h23, l23);
        uint2 uh; uh.x = h01; uh.y = h23;
        uint2 ul; ul.x = l01; ul.y = l23;
        *(uint2*)&g_agg_hi[n * D + c4] = uh;
        *(uint2*)&g_agg_lo[n * D + c4] = ul;
    }
}

// ---------------- mma.sync bf16-split GEMM (exact R8 structure, no stats) ----------------
// C[M,NC] = A[M,K]·Bt[NC,K]^T, A=Ahi+Alo, B=Bhi+Blo (bf16 split):
// C ≈ Ahi·Bhi + Ahi·Blo + Alo·Bhi  (fp32 accumulate)
// BM=128, BN=64, BK=64. 256 thr = 8 warps (4x2), warp tile 32x32.
#define SA_HI 0
#define SA_LO 16384
#define SB_HI 32768
#define SB_LO 40960
#define SM_TOTAL 49152

__device__ __forceinline__ void ldTileA(char* sm, int soff,
                                        const __nv_bfloat16* __restrict__ src,
                                        int row0, int stride, int k0, int mval) {
#pragma unroll
    for (int i = 0; i < 4; i++) {
        int t = threadIdx.x + i * 256;
        int r = t >> 3, c8 = t & 7;
        uint4 v = make_uint4(0u, 0u, 0u, 0u);
        if (r < mval) v = *(const uint4*)&src[(long)(row0 + r) * stride + k0 + c8 * 8];
        *(uint4*)(sm + soff + r * 128 + ((c8 ^ (r & 7)) << 4)) = v;
    }
}
__device__ __forceinline__ void ldTileB(char* sm, int soff,
                                        const __nv_bfloat16* __restrict__ src,
                                        int row0, int stride, int k0) {
#pragma unroll
    for (int i = 0; i < 2; i++) {
        int t = threadIdx.x + i * 256;
        int r = t >> 3, c8 = t & 7;
        uint4 v = *(const uint4*)&src[(long)(row0 + r) * stride + k0 + c8 * 8];
        *(uint4*)(sm + soff + r * 128 + ((c8 ^ (r & 7)) << 4)) = v;
    }
}

__global__ void __launch_bounds__(256)
k_gemm_mma(const __nv_bfloat16* __restrict__ Ahi, const __nv_bfloat16* __restrict__ Alo,
           const __nv_bfloat16* __restrict__ Bhi, const __nv_bfloat16* __restrict__ Blo,
           const float* __restrict__ bias,
           float* __restrict__ outF,
           __nv_bfloat16* __restrict__ outHi, __nv_bfloat16* __restrict__ outLo,
           int M, int Kin, int NC, int relu_mode) {
    extern __shared__ char sm[];
    uint32_t sb = smem_u32(sm);
    int tid = threadIdx.x, wid = tid >> 5, lane = tid & 31;
    int wm = wid >> 1, wn = wid & 1;
    int m0 = blockIdx.x * 128;
    int n0 = blockIdx.y * 64;
    int mvalid = M - m0; if (mvalid > 128) mvalid = 128;

    float acc[2][4][4];
#pragma unroll
    for (int mt = 0; mt < 2; mt++)
#pragma unroll
        for (int nt = 0; nt < 4; nt++)
#pragma unroll
            for (int q = 0; q < 4; q++) acc[mt][nt][q] = 0.f;

    int chunks = Kin >> 6;
    for (int ch = 0; ch < chunks; ch++) {
        int k0 = ch << 6;
        ldTileA(sm, SA_HI, Ahi, m0, Kin, k0, mvalid);
        ldTileA(sm, SA_LO, Alo, m0, Kin, k0, mvalid);
        ldTileB(sm, SB_HI, Bhi, n0, Kin, k0);
        ldTileB(sm, SB_LO, Blo, n0, Kin, k0);
        __syncthreads();

#pragma unroll
        for (int ks = 0; ks < 4; ks++) {
            uint32_t ah[2][4], al[2][4], bh[4][2], bl[4][2];
            int arow_l = lane & 15;
            int ac8 = ks * 2 + (lane >> 4);
#pragma unroll
            for (int mt = 0; mt < 2; mt++) {
                int r = wm * 32 + mt * 16 + arow_l;
                uint32_t ad = sb + r * 128 + ((ac8 ^ (r & 7)) << 4);
                ldm4(ah[mt][0], ah[mt][1], ah[mt][2], ah[mt][3], ad + SA_HI);
                ldm4(al[mt][0], al[mt][1], al[mt][2], al[mt][3], ad + SA_LO);
            }
            int nrow_l = (lane & 7) + ((lane >> 4) << 3);
            int bc8 = ks * 2 + ((lane >> 3) & 1);
#pragma unroll
            for (int p = 0; p < 2; p++) {
                int r = wn * 32 + p * 16 + nrow_l;
                uint32_t bd = sb + r * 128 + ((bc8 ^ (r & 7)) << 4);
                ldm4(bh[2 * p][0], bh[2 * p][1], bh[2 * p + 1][0], bh[2 * p + 1][1], bd + SB_HI);
                ldm4(bl[2 * p][0], bl[2 * p][1], bl[2 * p + 1][0], bl[2 * p + 1][1], bd + SB_LO);
            }
#pragma unroll
            for (int mt = 0; mt < 2; mt++)
#pragma unroll
                for (int nt = 0; nt < 4; nt++) {
                    mma_bf16(acc[mt][nt], ah[mt], bh[nt]);
                    mma_bf16(acc[mt][nt], ah[mt], bl[nt]);
                    mma_bf16(acc[mt][nt], al[mt], bh[nt]);
                }
        }
        __syncthreads();
    }

    // epilogue
#pragma unroll
    for (int mt = 0; mt < 2; mt++) {
        int r0 = m0 + wm * 32 + mt * 16 + (lane >> 2);
#pragma unroll
        for (int nt = 0; nt < 4; nt++) {
            int cb = n0 + wn * 32 + nt * 8 + (lane & 3) * 2;
            float b0 = bias[cb], b1 = bias[cb + 1];
            float v0 = acc[mt][nt][0] + b0;
            float v1 = acc[mt][nt][1] + b1;
            float v2 = acc[mt][nt][2] + b0;
            float v3 = acc[mt][nt][3] + b1;
            if (relu_mode) {
                v0 = fmaxf(v0, 0.f); v1 = fmaxf(v1, 0.f);
                v2 = fmaxf(v2, 0.f); v3 = fmaxf(v3, 0.f);
                uint32_t h01, l01, h23, l23;
                split2(v0, v1, h01, l01);
                split2(v2, v3, h23, l23);
                if (r0 < M) {
                    *(uint32_t*)&outHi[(long)r0 * NC + cb] = h01;
                    *(uint32_t*)&outLo[(long)r0 * NC + cb] = l01;
                }
                if (r0 + 8 < M) {
                    *(uint32_t*)&outHi[(long)(r0 + 8) * NC + cb] = h23;
                    *(uint32_t*)&outLo[(long)(r0 + 8) * NC + cb] = l23;
                }
            } else {
                if (r0 < M) {
                    float2 p; p.x = v0; p.y = v1;
                    *(float2*)&outF[(long)r0 * NC + cb] = p;
                }
                if (r0 + 8 < M) {
                    float2 p; p.x = v2; p.y = v3;
                    *(float2*)&outF[(long)(r0 + 8) * NC + cb] = p;
                }
            }
        }
    }
}

// ---------------- BN stats / final norm (R8-proven separate kernels) ----------------
__global__ void k_colstats() {
    int col = threadIdx.x;
    float s1 = 0.f, s2 = 0.f;
    for (int r = blockIdx.x; r < NN; r += STATS_BLOCKS) {
        float v = g_h2[r * D + col];
        s1 += v;
        s2 += v * v;
    }
    g_p1[blockIdx.x * D + col] = s1;
    g_p2[blockIdx.x * D + col] = s2;
}

__global__ void k_bnfinal(const float* __restrict__ gamma,
                          const float* __restrict__ beta) {
    int c = threadIdx.x;
    float s1 = 0.f, s2 = 0.f;
    for (int i = 0; i < STATS_BLOCKS; i++) {
        s1 += g_p1[i * D + c];
        s2 += g_p2[i * D + c];
    }
    float mu  = s1 / (float)NN;
    float var = s2 / (float)NN - mu * mu;
    float sc  = gamma[c] * rsqrtf(var + BN_EPS);
    g_scale[c] = sc;
    g_shift[c] = beta[c] - mu * sc;
}

__global__ void k_norm(float* __restrict__ dst) {
    int idx = blockIdx.x * blockDim.x + threadIdx.x;
    if (idx >= NN * 32) return;
    int c4 = (idx & 31) * 4;
    float4 v  = *(const float4*)&g_h2[idx * 4];
    float4 sc = *(const float4*)&g_scale[c4];
    float4 sh = *(const float4*)&g_shift[c4];
    float4 o;
    o.x = fmaf(sc.x, v.x, sh.x); o.y = fmaf(sc.y, v.y, sh.y);
    o.z = fmaf(sc.z, v.z, sh.z); o.w = fmaf(sc.w, v.w, sh.w);
    *(float4*)&dst[idx * 4] = o;
}

// ---------------- host ----------------
extern "C" void kernel_launch(void* const* d_in, const int* in_sizes, int n_in,
                              void* d_out, int out_size) {
    const int*   x     = (const int*)d_in[0];
    const int*   ei    = (const int*)d_in[1];
    const int*   ea    = (const int*)d_in[2];
    const float* ae    = (const float*)d_in[3];
    const float* ce    = (const float*)d_in[4];
    const float* he    = (const float*)d_in[5];
    const float* e1    = (const float*)d_in[6];
    const float* e2    = (const float*)d_in[7];
    const float* W1    = (const float*)d_in[8];
    const float* b1    = (const float*)d_in[9];
    const float* W2    = (const float*)d_in[10];
    const float* b2    = (const float*)d_in[11];
    const float* gamma = (const float*)d_in[12];
    const float* beta  = (const float*)d_in[13];
    float* out = (float*)d_out;

    void *p_h, *p_h2, *p_agh, *p_agl, *p_th, *p_tl, *p_w1h, *p_w1l, *p_w2h, *p_w2l;
    cudaGetSymbolAddress(&p_h,   g_h);
    cudaGetSymbolAddress(&p_h2,  g_h2);
    cudaGetSymbolAddress(&p_agh, g_agg_hi);
    cudaGetSymbolAddress(&p_agl, g_agg_lo);
    cudaGetSymbolAddress(&p_th,  g_t_hi);
    cudaGetSymbolAddress(&p_tl,  g_t_lo);
    cudaGetSymbolAddress(&p_w1h, g_w1t_hi);
    cudaGetSymbolAddress(&p_w1l, g_w1t_lo);
    cudaGetSymbolAddress(&p_w2h, g_w2t_hi);
    cudaGetSymbolAddress(&p_w2l, g_w2t_lo);
    float* hv  = (float*)p_h;
    float* h2v = (float*)p_h2;
    __nv_bfloat16* agh = (__nv_bfloat16*)p_agh;
    __nv_bfloat16* agl = (__nv_bfloat16*)p_agl;
    __nv_bfloat16* th  = (__nv_bfloat16*)p_th;
    __nv_bfloat16* tl  = (__nv_bfloat16*)p_tl;
    __nv_bfloat16* w1h = (__nv_bfloat16*)p_w1h;
    __nv_bfloat16* w1l = (__nv_bfloat16*)p_w1l;
    __nv_bfloat16* w2h = (__nv_bfloat16*)p_w2h;
    __nv_bfloat16* w2l = (__nv_bfloat16*)p_w2l;

    cudaFuncSetAttribute(k_gemm_mma, cudaFuncAttributeMaxDynamicSharedMemorySize, SM_TOTAL);

    const int vecBlocks  = (NN * 32 + 255) / 256;
    const int nodeBlocks = (NN + 255) / 256;
    const int edgeBlocks = (NE + 255) / 256;
    const int aggBlocks  = (NN + 31) / 32;       // 1563 (4 nodes/warp — measured fast)
    const int mTiles     = (NN + 127) / 128;     // 391
    const int prepBlocks = (NUM_LAYER * 256 * 128 + 255) / 256;

    k_embed<<<vecBlocks, 256>>>(x, ae, ce, he);
    k_prepw<<<prepBlocks, 256>>>(W1, W2);
    k_zero_deg<<<nodeBlocks, 256>>>();
    k_count<<<edgeBlocks, 256>>>(ei);
    k_scan1<<<SCAN_BLOCKS, 1024>>>();
    k_scan2<<<1, 1>>>();
    k_scan3<<<SCAN_BLOCKS, 1024>>>();
    k_fill<<<edgeBlocks, 256>>>(ei, ea);

    for (int l = 0; l < NUM_LAYER; l++) {
        k_agg<<<aggBlocks, 256>>>(e1 + (long)l * 6 * D, e2 + (long)l * 4 * D,
                                  (l == 0) ? hv : h2v, (l == 0) ? 0 : 1);
        // GEMM1: [NN,128] x W1t[256,128]^T -> t (bf16 hi/lo, relu)
        k_gemm_mma<<<dim3(mTiles, 4), 256, SM_TOTAL>>>(
            agh, agl,
            w1h + (long)l * 256 * 128, w1l + (long)l * 256 * 128,
            b1 + (long)l * 256,
            nullptr, th, tl,
            NN, 128, 256, 1);
        // GEMM2: [NN,256] x W2t[128,256]^T -> g_h2 (fp32)
        k_gemm_mma<<<dim3(mTiles, 2), 256, SM_TOTAL>>>(
            th, tl,
            w2h + (long)l * 128 * 256, w2l + (long)l * 128 * 256,
            b2 + (long)l * D,
            h2v, nullptr, nullptr,
            NN, 256, 128, 0);
        k_colstats<<<STATS_BLOCKS, 128>>>();
        k_bnfinal<<<1, 128>>>(gamma + (long)l * D, beta + (long)l * D);
    }
    k_norm<<<vecBlocks, 256>>>(out);
}

// round 14
// speedup vs baseline: 1.5798x; 1.0173x over previous
#include <cuda_runtime.h>
#include <cuda_bf16.h>
#include <cstdint>

#define NN 50000
#define NE 600000
#define D  128
#define NUM_LAYER 5
#define BN_EPS 1e-5f
#define STATS_BLOCKS 512
#define SCAN_BLOCKS 49   // ceil(50000/1024)

// ---------------- scratch (static device globals; no allocation) ----------------
__device__ float g_h  [NN * D];     // node features after input embedding
__device__ float g_h2 [NN * D];     // after Linear2 (pre-BN)
__device__ __nv_bfloat16 g_agg_hi[NN * D];
__device__ __nv_bfloat16 g_agg_lo[NN * D];
__device__ __nv_bfloat16 g_t_hi[NN * 256];
__device__ __nv_bfloat16 g_t_lo[NN * 256];
__device__ __nv_bfloat16 g_w1t_hi[NUM_LAYER * 256 * 128];  // [l][n][k]
__device__ __nv_bfloat16 g_w1t_lo[NUM_LAYER * 256 * 128];
__device__ __nv_bfloat16 g_w2t_hi[NUM_LAYER * 128 * 256];  // [l][n][k]
__device__ __nv_bfloat16 g_w2t_lo[NUM_LAYER * 128 * 256];
__device__ int   g_deg[NN];
__device__ int   g_off[NN + 1];
__device__ int   g_cur[NN];
__device__ int   g_src [NE];
__device__ int   g_code[NE];
__device__ int   g_bsum[SCAN_BLOCKS];
__device__ int   g_boff[SCAN_BLOCKS];
__device__ float g_p1[STATS_BLOCKS * D];
__device__ float g_p2[STATS_BLOCKS * D];
__device__ float g_scale[D];
__device__ float g_shift[D];

// ---------------- small helpers ----------------
__device__ __forceinline__ uint32_t smem_u32(const void* p) {
    uint32_t a;
    asm("{ .reg .u64 t; cvta.to.shared.u64 t, %1; cvt.u32.u64 %0, t; }" : "=r"(a) : "l"(p));
    return a;
}
__device__ __forceinline__ void split2(float a, float b, uint32_t& h, uint32_t& l) {
    __nv_bfloat16 ah = __float2bfloat16(a), bh = __float2bfloat16(b);
    __nv_bfloat16 al = __float2bfloat16(a - __bfloat162float(ah));
    __nv_bfloat16 bl = __float2bfloat16(b - __bfloat162float(bh));
    __nv_bfloat162 hh; hh.x = ah; hh.y = bh;
    __nv_bfloat162 ll; ll.x = al; ll.y = bl;
    h = *(uint32_t*)&hh;
    l = *(uint32_t*)&ll;
}
__device__ __forceinline__ void ldm4(uint32_t& r0, uint32_t& r1, uint32_t& r2, uint32_t& r3,
                                     uint32_t addr) {
    asm volatile("ldmatrix.sync.aligned.m8n8.x4.shared.b16 {%0,%1,%2,%3}, [%4];"
                 : "=r"(r0), "=r"(r1), "=r"(r2), "=r"(r3) : "r"(addr));
}
__device__ __forceinline__ void mma_bf16(float* c, const uint32_t* a, const uint32_t* b) {
    asm volatile(
        "mma.sync.aligned.m16n8k16.row.col.f32.bf16.bf16.f32 "
        "{%0,%1,%2,%3},{%4,%5,%6,%7},{%8,%9},{%0,%1,%2,%3};"
        : "+f"(c[0]), "+f"(c[1]), "+f"(c[2]), "+f"(c[3])
        : "r"(a[0]), "r"(a[1]), "r"(a[2]), "r"(a[3]), "r"(b[0]), "r"(b[1]));
}
// swizzled 16B-group index for 256B rows (16 groups/row): bank-conflict-free
__device__ __forceinline__ uint32_t swz16(uint32_t g, uint32_t r) {
    return ((g ^ r) & 7u) | (g & 8u);
}

// ---------------- preamble kernels ----------------

__global__ void k_embed(const int* __restrict__ x,
                        const float* __restrict__ ae,
                        const float* __restrict__ ce,
                        const float* __restrict__ he) {
    int idx = blockIdx.x * blockDim.x + threadIdx.x;       // over NN*32
    if (idx >= NN * 32) return;
    int n  = idx >> 5;
    int c4 = (idx & 31) * 4;
    int x0 = x[n * 3 + 0], x1 = x[n * 3 + 1], x2 = x[n * 3 + 2];
    float4 a = *(const float4*)&ae[x0 * D + c4];
    float4 b = *(const float4*)&ce[x1 * D + c4];
    float4 c = *(const float4*)&he[x2 * D + c4];
    float4 o;
    o.x = a.x + b.x + c.x; o.y = a.y + b.y + c.y;
    o.z = a.z + b.z + c.z; o.w = a.w + b.w + c.w;
    *(float4*)&g_h[n * D + c4] = o;
}

__global__ void k_prepw(const float* __restrict__ W1, const float* __restrict__ W2) {
    int i = blockIdx.x * blockDim.x + threadIdx.x;
    if (i >= NUM_LAYER * 256 * 128) return;
    {
        int l = i / (256 * 128), rem = i % (256 * 128);
        int n = rem >> 7, k = rem & 127;
        float v = W1[(l * 128 + k) * 256 + n];
        __nv_bfloat16 h = __float2bfloat16(v);
        g_w1t_hi[i] = h;
        g_w1t_lo[i] = __float2bfloat16(v - __bfloat162float(h));
    }
    {
        int l = i / (128 * 256), rem = i % (128 * 256);
        int n = rem >> 8, k = rem & 255;
        float v = W2[(l * 256 + k) * 128 + n];
        __nv_bfloat16 h = __float2bfloat16(v);
        g_w2t_hi[i] = h;
        g_w2t_lo[i] = __float2bfloat16(v - __bfloat162float(h));
    }
}

__global__ void k_zero_deg() {
    int i = blockIdx.x * blockDim.x + threadIdx.x;
    if (i < NN) g_deg[i] = 0;
}

__global__ void k_count(const int* __restrict__ ei) {
    int e = blockIdx.x * blockDim.x + threadIdx.x;
    if (e < NE) atomicAdd(&g_deg[ei[NE + e]], 1);
}

__global__ void k_scan1() {
    __shared__ int swarp[32];
    int tid = threadIdx.x;
    int i = blockIdx.x * 1024 + tid;
    int v = (i < NN) ? g_deg[i] : 0;
    int x = v;
#pragma unroll
    for (int o = 1; o < 32; o <<= 1) {
        int t = __shfl_up_sync(0xffffffffu, x, o);
        if ((tid & 31) >= o) x += t;
    }
    if ((tid & 31) == 31) swarp[tid >> 5] = x;
    __syncthreads();
    if (tid < 32) {
        int y = swarp[tid];
#pragma unroll
        for (int o = 1; o < 32; o <<= 1) {
            int t = __shfl_up_sync(0xffffffffu, y, o);
            if (tid >= o) y += t;
        }
        swarp[tid] = y;
    }
    __syncthreads();
    int off = (tid >= 32) ? swarp[(tid >> 5) - 1] : 0;
    int incl = x + off;
    if (i < NN) g_off[i] = incl - v;
    if (tid == 1023) g_bsum[blockIdx.x] = incl;
}

__global__ void k_scan2() {
    int acc = 0;
#pragma unroll
    for (int b = 0; b < SCAN_BLOCKS; b++) {
        int t = g_bsum[b];
        g_boff[b] = acc;
        acc += t;
    }
    g_off[NN] = acc;
}

__global__ void k_scan3() {
    int i = blockIdx.x * 1024 + threadIdx.x;
    if (i < NN) {
        int o = g_off[i] + g_boff[i >> 10];
        g_off[i] = o;
        g_cur[i] = o;
    }
}

__global__ void k_fill(const int* __restrict__ ei, const int* __restrict__ ea) {
    int e = blockIdx.x * blockDim.x + threadIdx.x;
    if (e >= NE) return;
    int d = ei[NE + e];
    int p = atomicAdd(&g_cur[d], 1);
    g_src[p]  = ei[e];
    g_code[p] = ea[2 * e] * 4 + ea[2 * e + 1];
}

// 4 nodes per warp (measured fast shape). fuse=1 applies previous layer's
// BN+ReLU to gathered rows. Writes bf16 hi/lo split directly (GEMM1 input).
__global__ void k_agg(const float* __restrict__ e1l, const float* __restrict__ e2l,
                      const float* __restrict__ hin, int fuse) {
    __shared__ __align__(16) float see[24 * D];
    for (int i = threadIdx.x; i < 24 * D; i += 256) {
        int c = i >> 7, k = i & 127;
        see[i] = e1l[(c >> 2) * D + k] + e2l[(c & 3) * D + k];
    }
    __syncthreads();
    int warp = threadIdx.x >> 5;
    int lane = threadIdx.x & 31;
    int c4 = lane * 4;
    float4 sc = make_float4(1.f, 1.f, 1.f, 1.f);
    float4 sh = make_float4(0.f, 0.f, 0.f, 0.f);
    if (fuse) {
        sc = *(const float4*)&g_scale[c4];
        sh = *(const float4*)&g_shift[c4];
    }
#pragma unroll
    for (int i = 0; i < 4; i++) {
        int n = blockIdx.x * 32 + warp * 4 + i;
        if (n >= NN) continue;
        float4 acc = make_float4(0.f, 0.f, 0.f, 0.f);
        int b = g_off[n], e = g_off[n + 1];
        for (int j = b; j < e; j++) {
            int s0 = g_src[j], c0 = g_code[j];
            float4 h0 = *(const float4*)&hin[s0 * D + c4];
            float4 e0 = *(const float4*)&see[c0 * D + c4];
            if (fuse) {
                h0.x = fmaxf(fmaf(sc.x, h0.x, sh.x), 0.f);
                h0.y = fmaxf(fmaf(sc.y, h0.y, sh.y), 0.f);
                h0.z = fmaxf(fmaf(sc.z, h0.z, sh.z), 0.f);
                h0.w = fmaxf(fmaf(sc.w, h0.w, sh.w), 0.f);
            }
            acc.x += h0.x + e0.x;
            acc.y += h0.y + e0.y;
            acc.z += h0.z + e0.z;
            acc.w += h0.w + e0.w;
        }
        uint32_t h01, l01, h23, l23;
        split2(acc.x, acc.y, h01, l01);
        split2(acc.z, acc.w, h23, l23);
        uint2 uh; uh.x = h01; uh.y = h23;
        uint2 ul; ul.x = l01; ul.y = l23;
        *(uint2*)&g_agg_hi[n * D + c4] = uh;
        *(uint2*)&g_agg_lo[n * D + c4] = ul;
    }
}

// ---------------- GEMM1: A-resident, full K=128 in smem, loop 4 N-chunks ----------------
// t = relu(A·W1t^T + b1), output split to bf16 hi/lo.
// A tile: 128 rows x 256B (swz16) per component. B chunk: 64 rows x 256B per component.
#define G1_A_HI 0
#define G1_A_LO 32768
#define G1_B_HI 65536
#define G1_B_LO 81920
#define G1_SM   98304

__global__ void __launch_bounds__(256)
k_gemm1(const __nv_bfloat16* __restrict__ Ahi, const __nv_bfloat16* __restrict__ Alo,
        const __nv_bfloat16* __restrict__ Bhi, const __nv_bfloat16* __restrict__ Blo,
        const float* __restrict__ bias,
        __nv_bfloat16* __restrict__ outHi, __nv_bfloat16* __restrict__ outLo) {
    extern __shared__ char sm[];
    uint32_t sb = smem_u32(sm);
    int tid = threadIdx.x, wid = tid >> 5, lane = tid & 31;
    int wm = wid >> 1, wn = wid & 1;
    int m0 = blockIdx.x * 128;
    int mvalid = NN - m0; if (mvalid > 128) mvalid = 128;

    // load A once: per component 128 rows x 16 groups = 2048 uint4 (8/thread)
#pragma unroll
    for (int i = 0; i < 8; i++) {
        int t = tid + i * 256;
        uint32_t r = (uint32_t)(t >> 4), c8 = (uint32_t)(t & 15);
        uint32_t off = r * 256 + swz16(c8, r & 7) * 16;
        uint4 vh = make_uint4(0u, 0u, 0u, 0u), vl = make_uint4(0u, 0u, 0u, 0u);
        if ((int)r < mvalid) {
            vh = *(const uint4*)&Ahi[(long)(m0 + r) * 128 + c8 * 8];
            vl = *(const uint4*)&Alo[(long)(m0 + r) * 128 + c8 * 8];
        }
        *(uint4*)(sm + G1_A_HI + off) = vh;
        *(uint4*)(sm + G1_A_LO + off) = vl;
    }

    int arow_l = lane & 15;
    int nrow_l = (lane & 7) + ((lane >> 4) << 3);

    for (int nchunk = 0; nchunk < 4; nchunk++) {
        int nc0 = nchunk * 64;
        __syncthreads();   // previous chunk's readers done before B overwrite
        // load B chunk: per component 64 rows x 16 groups = 1024 uint4 (4/thread)
#pragma unroll
        for (int i = 0; i < 4; i++) {
            int t = tid + i * 256;
            uint32_t r = (uint32_t)(t >> 4), c8 = (uint32_t)(t & 15);
            uint32_t off = r * 256 + swz16(c8, r & 7) * 16;
            *(uint4*)(sm + G1_B_HI + off) = *(const uint4*)&Bhi[(long)(nc0 + r) * 128 + c8 * 8];
            *(uint4*)(sm + G1_B_LO + off) = *(const uint4*)&Blo[(long)(nc0 + r) * 128 + c8 * 8];
        }
        __syncthreads();

        float acc[2][4][4];
#pragma unroll
        for (int mt = 0; mt < 2; mt++)
#pragma unroll
            for (int nt = 0; nt < 4; nt++)
#pragma unroll
                for (int q = 0; q < 4; q++) acc[mt][nt][q] = 0.f;

#pragma unroll
        for (int ks = 0; ks < 8; ks++) {
            uint32_t ah[2][4], al[2][4], bh[4][2], bl[4][2];
            uint32_t ac8 = (uint32_t)(ks * 2 + (lane >> 4));
#pragma unroll
            for (int mt = 0; mt < 2; mt++) {
                uint32_t r = (uint32_t)(wm * 32 + mt * 16 + arow_l);
                uint32_t ad = sb + r * 256 + swz16(ac8, r & 7) * 16;
                ldm4(ah[mt][0], ah[mt][1], ah[mt][2], ah[mt][3], ad + G1_A_HI);
                ldm4(al[mt][0], al[mt][1], al[mt][2], al[mt][3], ad + G1_A_LO);
            }
            uint32_t bc8 = (uint32_t)(ks * 2 + ((lane >> 3) & 1));
#pragma unroll
            for (int p = 0; p < 2; p++) {
                uint32_t r = (uint32_t)(wn * 32 + p * 16 + nrow_l);
                uint32_t bd = sb + r * 256 + swz16(bc8, r & 7) * 16;
                ldm4(bh[2 * p][0], bh[2 * p][1], bh[2 * p + 1][0], bh[2 * p + 1][1], bd + G1_B_HI);
                ldm4(bl[2 * p][0], bl[2 * p][1], bl[2 * p + 1][0], bl[2 * p + 1][1], bd + G1_B_LO);
            }
#pragma unroll
            for (int mt = 0; mt < 2; mt++)
#pragma unroll
                for (int nt = 0; nt < 4; nt++) {
                    mma_bf16(acc[mt][nt], ah[mt], bh[nt]);
                    mma_bf16(acc[mt][nt], ah[mt], bl[nt]);
                    mma_bf16(acc[mt][nt], al[mt], bh[nt]);
                }
        }

        // epilogue for this 64-col chunk
#pragma unroll
        for (int mt = 0; mt < 2; mt++) {
            int r0 = m0 + wm * 32 + mt * 16 + (lane >> 2);
#pragma unroll
            for (int nt = 0; nt < 4; nt++) {
                int cb = nc0 + wn * 32 + nt * 8 + (lane & 3) * 2;
                float b0 = bias[cb], b1 = bias[cb + 1];
                float v0 = fmaxf(acc[mt][nt][0] + b0, 0.f);
                float v1 = fmaxf(acc[mt][nt][1] + b1, 0.f);
                float v2 = fmaxf(acc[mt][nt][2] + b0, 0.f);
                float v3 = fmaxf(acc[mt][nt][3] + b1, 0.f);
                uint32_t h01, l01, h23, l23;
                split2(v0, v1, h01, l01);
                split2(v2, v3, h23, l23);
                if (r0 < NN) {
                    *(uint32_t*)&outHi[(long)r0 * 256 + cb] = h01;
                    *(uint32_t*)&outLo[(long)r0 * 256 + cb] = l01;
                }
                if (r0 + 8 < NN) {
                    *(uint32_t*)&outHi[(long)(r0 + 8) * 256 + cb] = h23;
                    *(uint32_t*)&outLo[(long)(r0 + 8) * 256 + cb] = l23;
                }
            }
        }
    }
}

// ---------------- GEMM2: exact R12-proven kernel ----------------
#define SA_HI 0
#define SA_LO 16384
#define SB_HI 32768
#define SB_LO 40960
#define SM_TOTAL 49152

__device__ __forceinline__ void ldTileA(char* sm, int soff,
                                        const __nv_bfloat16* __restrict__ src,
                                        int row0, int stride, int k0, int mval) {
#pragma unroll
    for (int i = 0; i < 4; i++) {
        int t = threadIdx.x + i * 256;
        int r = t >> 3, c8 = t & 7;
        uint4 v = make_uint4(0u, 0u, 0u, 0u);
        if (r < mval) v = *(const uint4*)&src[(long)(row0 + r) * stride + k0 + c8 * 8];
        *(uint4*)(sm + soff + r * 128 + ((c8 ^ (r & 7)) << 4)) = v;
    }
}
__device__ __forceinline__ void ldTileB(char* sm, int soff,
                                        const __nv_bfloat16* __restrict__ src,
                                        int row0, int stride, int k0) {
#pragma unroll
    for (int i = 0; i < 2; i++) {
        int t = threadIdx.x + i * 256;
        int r = t >> 3, c8 = t & 7;
        uint4 v = *(const uint4*)&src[(long)(row0 + r) * stride + k0 + c8 * 8];
        *(uint4*)(sm + soff + r * 128 + ((c8 ^ (r & 7)) << 4)) = v;
    }
}

__global__ void __launch_bounds__(256)
k_gemm_mma(const __nv_bfloat16* __restrict__ Ahi, const __nv_bfloat16* __restrict__ Alo,
           const __nv_bfloat16* __restrict__ Bhi, const __nv_bfloat16* __restrict__ Blo,
           const float* __restrict__ bias,
           float* __restrict__ outF,
           int M, int Kin, int NC) {
    extern __shared__ char sm[];
    uint32_t sb = smem_u32(sm);
    int tid = threadIdx.x, wid = tid >> 5, lane = tid & 31;
    int wm = wid >> 1, wn = wid & 1;
    int m0 = blockIdx.x * 128;
    int n0 = blockIdx.y * 64;
    int mvalid = M - m0; if (mvalid > 128) mvalid = 128;

    float acc[2][4][4];
#pragma unroll
    for (int mt = 0; mt < 2; mt++)
#pragma unroll
        for (int nt = 0; nt < 4; nt++)
#pragma unroll
            for (int q = 0; q < 4; q++) acc[mt][nt][q] = 0.f;

    int chunks = Kin >> 6;
    for (int ch = 0; ch < chunks; ch++) {
        int k0 = ch << 6;
        ldTileA(sm, SA_HI, Ahi, m0, Kin, k0, mvalid);
        ldTileA(sm, SA_LO, Alo, m0, Kin, k0, mvalid);
        ldTileB(sm, SB_HI, Bhi, n0, Kin, k0);
        ldTileB(sm, SB_LO, Blo, n0, Kin, k0);
        __syncthreads();

#pragma unroll
        for (int ks = 0; ks < 4; ks++) {
            uint32_t ah[2][4], al[2][4], bh[4][2], bl[4][2];
            int arow_l = lane & 15;
            int ac8 = ks * 2 + (lane >> 4);
#pragma unroll
            for (int mt = 0; mt < 2; mt++) {
                int r = wm * 32 + mt * 16 + arow_l;
                uint32_t ad = sb + r * 128 + ((ac8 ^ (r & 7)) << 4);
                ldm4(ah[mt][0], ah[mt][1], ah[mt][2], ah[mt][3], ad + SA_HI);
                ldm4(al[mt][0], al[mt][1], al[mt][2], al[mt][3], ad + SA_LO);
            }
            int nrow_l = (lane & 7) + ((lane >> 4) << 3);
            int bc8 = ks * 2 + ((lane >> 3) & 1);
#pragma unroll
            for (int p = 0; p < 2; p++) {
                int r = wn * 32 + p * 16 + nrow_l;
                uint32_t bd = sb + r * 128 + ((bc8 ^ (r & 7)) << 4);
                ldm4(bh[2 * p][0], bh[2 * p][1], bh[2 * p + 1][0], bh[2 * p + 1][1], bd + SB_HI);
                ldm4(bl[2 * p][0], bl[2 * p][1], bl[2 * p + 1][0], bl[2 * p + 1][1], bd + SB_LO);
            }
#pragma unroll
            for (int mt = 0; mt < 2; mt++)
#pragma unroll
                for (int nt = 0; nt < 4; nt++) {
                    mma_bf16(acc[mt][nt], ah[mt], bh[nt]);
                    mma_bf16(acc[mt][nt], ah[mt], bl[nt]);
                    mma_bf16(acc[mt][nt], al[mt], bh[nt]);
                }
        }
        __syncthreads();
    }

#pragma unroll
    for (int mt = 0; mt < 2; mt++) {
        int r0 = m0 + wm * 32 + mt * 16 + (lane >> 2);
#pragma unroll
        for (int nt = 0; nt < 4; nt++) {
            int cb = n0 + wn * 32 + nt * 8 + (lane & 3) * 2;
            float b0 = bias[cb], b1 = bias[cb + 1];
            float v0 = acc[mt][nt][0] + b0;
            float v1 = acc[mt][nt][1] + b1;
            float v2 = acc[mt][nt][2] + b0;
            float v3 = acc[mt][nt][3] + b1;
            if (r0 < M) {
                float2 p; p.x = v0; p.y = v1;
                *(float2*)&outF[(long)r0 * NC + cb] = p;
            }
            if (r0 + 8 < M) {
                float2 p; p.x = v2; p.y = v3;
                *(float2*)&outF[(long)(r0 + 8) * NC + cb] = p;
            }
        }
    }
}

// ---------------- BN stats / final norm ----------------
__global__ void k_colstats() {
    int col = threadIdx.x;
    float s1 = 0.f, s2 = 0.f;
    for (int r = blockIdx.x; r < NN; r += STATS_BLOCKS) {
        float v = g_h2[r * D + col];
        s1 += v;
        s2 += v * v;
    }
    g_p1[blockIdx.x * D + col] = s1;
    g_p2[blockIdx.x * D + col] = s2;
}

__global__ void k_bnfinal(const float* __restrict__ gamma,
                          const float* __restrict__ beta) {
    int c = threadIdx.x;
    float s1 = 0.f, s2 = 0.f;
    for (int i = 0; i < STATS_BLOCKS; i++) {
        s1 += g_p1[i * D + c];
        s2 += g_p2[i * D + c];
    }
    float mu  = s1 / (float)NN;
    float var = s2 / (float)NN - mu * mu;
    float sc  = gamma[c] * rsqrtf(var + BN_EPS);
    g_scale[c] = sc;
    g_shift[c] = beta[c] - mu * sc;
}

__global__ void k_norm(float* __restrict__ dst) {
    int idx = blockIdx.x * blockDim.x + threadIdx.x;
    if (idx >= NN * 32) return;
    int c4 = (idx & 31) * 4;
    float4 v  = *(const float4*)&g_h2[idx * 4];
    float4 sc = *(const float4*)&g_scale[c4];
    float4 sh = *(const float4*)&g_shift[c4];
    float4 o;
    o.x = fmaf(sc.x, v.x, sh.x); o.y = fmaf(sc.y, v.y, sh.y);
    o.z = fmaf(sc.z, v.z, sh.z); o.w = fmaf(sc.w, v.w, sh.w);
    *(float4*)&dst[idx * 4] = o;
}

// ---------------- host ----------------
extern "C" void kernel_launch(void* const* d_in, const int* in_sizes, int n_in,
                              void* d_out, int out_size) {
    const int*   x     = (const int*)d_in[0];
    const int*   ei    = (const int*)d_in[1];
    const int*   ea    = (const int*)d_in[2];
    const float* ae    = (const float*)d_in[3];
    const float* ce    = (const float*)d_in[4];
    const float* he    = (const float*)d_in[5];
    const float* e1    = (const float*)d_in[6];
    const float* e2    = (const float*)d_in[7];
    const float* W1    = (const float*)d_in[8];
    const float* b1    = (const float*)d_in[9];
    const float* W2    = (const float*)d_in[10];
    const float* b2    = (const float*)d_in[11];
    const float* gamma = (const float*)d_in[12];
    const float* beta  = (const float*)d_in[13];
    float* out = (float*)d_out;

    void *p_h, *p_h2, *p_agh, *p_agl, *p_th, *p_tl, *p_w1h, *p_w1l, *p_w2h, *p_w2l;
    cudaGetSymbolAddress(&p_h,   g_h);
    cudaGetSymbolAddress(&p_h2,  g_h2);
    cudaGetSymbolAddress(&p_agh, g_agg_hi);
    cudaGetSymbolAddress(&p_agl, g_agg_lo);
    cudaGetSymbolAddress(&p_th,  g_t_hi);
    cudaGetSymbolAddress(&p_tl,  g_t_lo);
    cudaGetSymbolAddress(&p_w1h, g_w1t_hi);
    cudaGetSymbolAddress(&p_w1l, g_w1t_lo);
    cudaGetSymbolAddress(&p_w2h, g_w2t_hi);
    cudaGetSymbolAddress(&p_w2l, g_w2t_lo);
    float* hv  = (float*)p_h;
    float* h2v = (float*)p_h2;
    __nv_bfloat16* agh = (__nv_bfloat16*)p_agh;
    __nv_bfloat16* agl = (__nv_bfloat16*)p_agl;
    __nv_bfloat16* th  = (__nv_bfloat16*)p_th;
    __nv_bfloat16* tl  = (__nv_bfloat16*)p_tl;
    __nv_bfloat16* w1h = (__nv_bfloat16*)p_w1h;
    __nv_bfloat16* w1l = (__nv_bfloat16*)p_w1l;
    __nv_bfloat16* w2h = (__nv_bfloat16*)p_w2h;
    __nv_bfloat16* w2l = (__nv_bfloat16*)p_w2l;

    cudaFuncSetAttribute(k_gemm1, cudaFuncAttributeMaxDynamicSharedMemorySize, G1_SM);
    cudaFuncSetAttribute(k_gemm_mma, cudaFuncAttributeMaxDynamicSharedMemorySize, SM_TOTAL);

    const int vecBlocks  = (NN * 32 + 255) / 256;
    const int nodeBlocks = (NN + 255) / 256;
    const int edgeBlocks = (NE + 255) / 256;
    const int aggBlocks  = (NN + 31) / 32;       // 1563 (4 nodes/warp)
    const int mTiles     = (NN + 127) / 128;     // 391
    const int prepBlocks = (NUM_LAYER * 256 * 128 + 255) / 256;

    k_embed<<<vecBlocks, 256>>>(x, ae, ce, he);
    k_prepw<<<prepBlocks, 256>>>(W1, W2);
    k_zero_deg<<<nodeBlocks, 256>>>();
    k_count<<<edgeBlocks, 256>>>(ei);
    k_scan1<<<SCAN_BLOCKS, 1024>>>();
    k_scan2<<<1, 1>>>();
    k_scan3<<<SCAN_BLOCKS, 1024>>>();
    k_fill<<<edgeBlocks, 256>>>(ei, ea);

    for (int l = 0; l < NUM_LAYER; l++) {
        k_agg<<<aggBlocks, 256>>>(e1 + (long)l * 6 * D, e2 + (long)l * 4 * D,
                                  (l == 0) ? hv : h2v, (l == 0) ? 0 : 1);
        // GEMM1 (A-resident): [NN,128] x W1t[256,128]^T -> t (bf16 hi/lo, relu)
        k_gemm1<<<mTiles, 256, G1_SM>>>(
            agh, agl,
            w1h + (long)l * 256 * 128, w1l + (long)l * 256 * 128,
            b1 + (long)l * 256,
            th, tl);
        // GEMM2: [NN,256] x W2t[128,256]^T -> g_h2 (fp32)
        k_gemm_mma<<<dim3(mTiles, 2), 256, SM_TOTAL>>>(
            th, tl,
            w2h + (long)l * 128 * 256, w2l + (long)l * 128 * 256,
            b2 + (long)l * D,
            h2v,
            NN, 256, 128);
        k_colstats<<<STATS_BLOCKS, 128>>>();
        k_bnfinal<<<1, 128>>>(gamma + (long)l * D, beta + (long)l * D);
    }
    k_norm<<<vecBlocks, 256>>>(out);
}